// round 3
// baseline (speedup 1.0000x reference)
#include <cuda_runtime.h>
#include <cstdint>

#define B_  1024
#define T_  32
#define D_  64
#define E_  100000
#define L_  50
#define NUM_BAGS (B_ * T_)        // 32768
#define BAGS_PER_CTA 8
#define THREADS 256

// One warp per bag. Two rows in flight per LDG batch entry:
//   lanes 0-15  handle rows at even positions (float4 slice lane&15)
//   lanes 16-31 handle rows at odd  positions
// Each LDG.128 instruction moves 512B/warp. Batch of 5 -> 2560B in flight
// with only 20 registers. Bags remapped so consecutive CTAs share a table
// (concurrent wave footprint fits L2 for repeat rows).
__global__ void __launch_bounds__(THREADS, 8)
embedding_bags_kernel(const float* __restrict__ weights,   // (E, T, D)
                      const int*   __restrict__ features,  // (B*T*L)
                      float*       __restrict__ out)       // (B*T, D)
{
    __shared__ int sidx[BAGS_PER_CTA * L_];    // 400 ints

    const int warpInBlk = threadIdx.x >> 5;
    const int lane      = threadIdx.x & 31;
    const int half      = lane >> 4;           // 0: even rows, 1: odd rows
    const int sub       = lane & 15;           // float4 slice within row

    const int new_bag_base = blockIdx.x * BAGS_PER_CTA;

    // ---- Stage this CTA's 8*50 indices into smem ----
    for (int i = threadIdx.x; i < BAGS_PER_CTA * L_; i += THREADS) {
        int w        = i / L_;
        int j        = i - w * L_;
        int new_bag  = new_bag_base + w;
        int t        = new_bag >> 10;
        int b        = new_bag & 1023;
        int bag_orig = (b << 5) | t;           // b*32 + t
        sidx[i] = features[(size_t)bag_orig * L_ + j];
    }
    __syncthreads();

    const int new_bag  = new_bag_base + warpInBlk;
    const int t        = new_bag >> 10;
    const int b        = new_bag & 1023;
    const int bag_orig = (b << 5) | t;

    // row (idx, t) starts at (idx*T + t)*D floats; as float4: idx*(T*D/4) + t*(D/4) + sub
    const float4* __restrict__ base =
        reinterpret_cast<const float4*>(weights) + (size_t)t * (D_ / 4) + sub;

    const int* __restrict__ myidx = sidx + warpInBlk * L_;

    float4 acc = make_float4(0.0f, 0.0f, 0.0f, 0.0f);

    // 25 row-pairs, in 5 batches of 5 independent LDG.128s (512B/warp each)
    #pragma unroll
    for (int m = 0; m < 5; ++m) {
        float4 v[5];
        #pragma unroll
        for (int p = 0; p < 5; ++p) {
            int q   = m * 5 + p;                    // pair index 0..24
            int idx = myidx[2 * q + half];          // LDS, 2 bcast addrs/warp
            v[p] = __ldg(base + (size_t)idx * (T_ * D_ / 4));
        }
        #pragma unroll
        for (int p = 0; p < 5; ++p) {
            acc.x += v[p].x;  acc.y += v[p].y;
            acc.z += v[p].z;  acc.w += v[p].w;
        }
    }

    // Merge even-row half and odd-row half
    acc.x += __shfl_xor_sync(0xffffffffu, acc.x, 16);
    acc.y += __shfl_xor_sync(0xffffffffu, acc.y, 16);
    acc.z += __shfl_xor_sync(0xffffffffu, acc.z, 16);
    acc.w += __shfl_xor_sync(0xffffffffu, acc.w, 16);

    if (half == 0) {
        reinterpret_cast<float4*>(out)[(size_t)bag_orig * (D_ / 4) + sub] = acc;
    }
}

extern "C" void kernel_launch(void* const* d_in, const int* in_sizes, int n_in,
                              void* d_out, int out_size)
{
    const float* weights  = (const float*)d_in[0];
    const int*   features = (const int*)  d_in[1];
    float* out = (float*)d_out;

    const int blocks = NUM_BAGS / BAGS_PER_CTA;   // 4096
    embedding_bags_kernel<<<blocks, THREADS>>>(weights, features, out);
}

// round 4
// speedup vs baseline: 1.0423x; 1.0423x over previous
#include <cuda_runtime.h>
#include <cstdint>

#define B_  1024
#define T_  32
#define D_  64
#define E_  100000
#define L_  50
#define NUM_BAGS (B_ * T_)        // 32768
#define THREADS 64
#define BAGS_PER_CTA 2

// One warp per bag. Gather rows via cp.async.cg (LDGSTS) into smem:
//  - lanes 0-15 fetch the even row of a pair, lanes 16-31 the odd row,
//    each lane one 16B chunk -> 512B per cp.async instruction.
//  - all 25 pair-loads issued up front (5 commit groups), progressive
//    wait_group + reduce keeps ~20 loads (10KB) in flight per warp.
// This sidesteps the per-SM LDG/MSHR outstanding cap (no depth cap observed
// for LDGSTS) and frees registers. Table-grouped bag remap keeps the
// concurrent wave's footprint small for L2 reuse of repeated rows.

template<int N>
__device__ __forceinline__ void cp_wait_group() {
    asm volatile("cp.async.wait_group %0;\n" :: "n"(N) : "memory");
}

__global__ void __launch_bounds__(THREADS, 8)
embedding_bags_kernel(const float* __restrict__ weights,   // (E, T, D)
                      const int*   __restrict__ features,  // (B*T*L)
                      float*       __restrict__ out)       // (B*T, D)
{
    __shared__ __align__(16) float4 srows[BAGS_PER_CTA * L_ * 16]; // 25600B
    __shared__ int sidx[BAGS_PER_CTA * 64];                        // 512B

    const int warp = threadIdx.x >> 5;
    const int lane = threadIdx.x & 31;
    const int half = lane >> 4;            // 0: even row of pair, 1: odd
    const int sub  = lane & 15;            // 16B chunk within 256B row

    // Table-grouped remap: new_bag = t*1024 + b  ->  orig bag = b*32 + t
    const int new_bag  = blockIdx.x * BAGS_PER_CTA + warp;
    const int t        = new_bag >> 10;
    const int b        = new_bag & 1023;
    const int bag_orig = (b << 5) | t;

    // Stage this warp's 50 indices into smem (2 coalesced LDGs), then
    // read them back with uniform LDS (cheap broadcast, no shfl chain).
    const int* __restrict__ idxp = features + (size_t)bag_orig * L_;
    int* __restrict__ myidx = sidx + warp * 64;
    myidx[lane] = __ldg(idxp + lane);
    if (lane < (L_ - 32)) myidx[32 + lane] = __ldg(idxp + 32 + lane);
    __syncwarp();

    // row (idx, t) starts at (idx*T + t)*D floats = float4 idx*512 + t*16
    const float4* __restrict__ gbase =
        reinterpret_cast<const float4*>(weights) + (size_t)t * (D_ / 4) + sub;

    float4* __restrict__ sbuf = srows + warp * (L_ * 16);
    const uint32_t sbase = (uint32_t)__cvta_generic_to_shared(sbuf);

    // Issue 25 pair-loads in 5 commit groups (all independent)
    #pragma unroll
    for (int g = 0; g < 5; ++g) {
        #pragma unroll
        for (int p = 0; p < 5; ++p) {
            const int q = g * 5 + p;          // pair 0..24
            const int r = 2 * q + half;       // row slot 0..49
            const int idx = myidx[r];
            const float4* src = gbase + (size_t)idx * (T_ * D_ / 4);
            const uint32_t dst = sbase + (uint32_t)(r * 256 + sub * 16);
            asm volatile("cp.async.cg.shared.global [%0], [%1], 16;\n"
                         :: "r"(dst), "l"(src) : "memory");
        }
        asm volatile("cp.async.commit_group;\n" ::: "memory");
    }

    float4 acc = make_float4(0.0f, 0.0f, 0.0f, 0.0f);

    // Progressive reduce: group g is complete once <= (4-g) groups pending.
    // Each lane reads back only bytes it wrote itself -> no syncwarp needed.
#define REDUCE_GROUP(G)                                              \
    cp_wait_group<4 - (G)>();                                        \
    _Pragma("unroll")                                                \
    for (int p = 0; p < 5; ++p) {                                    \
        const int r = 2 * ((G) * 5 + p) + half;                      \
        float4 v = sbuf[r * 16 + sub];                               \
        acc.x += v.x; acc.y += v.y; acc.z += v.z; acc.w += v.w;      \
    }

    REDUCE_GROUP(0)
    REDUCE_GROUP(1)
    REDUCE_GROUP(2)
    REDUCE_GROUP(3)
    REDUCE_GROUP(4)
#undef REDUCE_GROUP

    // Merge even-row half and odd-row half
    acc.x += __shfl_xor_sync(0xffffffffu, acc.x, 16);
    acc.y += __shfl_xor_sync(0xffffffffu, acc.y, 16);
    acc.z += __shfl_xor_sync(0xffffffffu, acc.z, 16);
    acc.w += __shfl_xor_sync(0xffffffffu, acc.w, 16);

    if (half == 0) {
        reinterpret_cast<float4*>(out)[(size_t)bag_orig * (D_ / 4) + sub] = acc;
    }
}

extern "C" void kernel_launch(void* const* d_in, const int* in_sizes, int n_in,
                              void* d_out, int out_size)
{
    const float* weights  = (const float*)d_in[0];
    const int*   features = (const int*)  d_in[1];
    float* out = (float*)d_out;

    const int blocks = NUM_BAGS / BAGS_PER_CTA;   // 16384
    embedding_bags_kernel<<<blocks, THREADS>>>(weights, features, out);
}